// round 5
// baseline (speedup 1.0000x reference)
#include <cuda_runtime.h>
#include <cuda_bf16.h>
#include <cuda_fp16.h>
#include <cstdint>

// ============================================================================
// out[b,o] = log( sum_k e^x[b,k] * e^w[o,k] ) - log( sum_k e^w[o,k] )
// Single fused kernel: split-K bf16 MMA GEMM -> software grid barrier ->
// in-kernel split reduce + log epilogue. Grid = 128 blocks = 1 wave (148 SMs),
// so the spin barrier is deadlock-free.
// ============================================================================

#define B_DIM  128
#define O_DIM  128
#define K_DIM  16384
#define NSPLIT 128
#define KCHUNK 128
#define NSUB   4
#define KSUB   32
#define LDSR   40     // smem row stride (bf16): 80B, conflict-free ldmatrix

// Transposed partials: [b][sp][o2] -> reduce phase reads contiguous 32KB/block
__device__ __half2 g_part[B_DIM * NSPLIT * (O_DIM / 2)];
__device__ float   g_rpart[NSPLIT * O_DIM];     // [sp][o]
__device__ int     g_arrive;                    // monotonic across replays
__device__ int     g_epoch;                     // monotonic across replays

__device__ __forceinline__ uint32_t smem_u32(const void* p) {
    return (uint32_t)__cvta_generic_to_shared(p);
}
__device__ __forceinline__ uint32_t bf2_bits(__nv_bfloat162 v) {
    union { __nv_bfloat162 h; uint32_t u; } cvt; cvt.h = v; return cvt.u;
}

__global__ __launch_bounds__(512, 1)
void srl_fused_kernel(const float* __restrict__ x, const float* __restrict__ w,
                      float* __restrict__ out) {
    __shared__ __align__(16) __nv_bfloat16 sA[2][B_DIM * LDSR];
    __shared__ __align__(16) __nv_bfloat16 sB[2][B_DIM * LDSR];

    const int tid  = threadIdx.x;
    const int lane = tid & 31;
    const int wid  = tid >> 5;
    const int bid  = blockIdx.x;        // = split index sp, and = batch row b
    const int kbase = bid * KCHUNK;

    // Loaders: 4 threads/row, 8 contiguous k (32B) each per stage.
    const int lrow = tid >> 2;
    const int kq   = tid & 3;
    const float4* xp4 = (const float4*)(x + (size_t)lrow * K_DIM + kbase + kq * 8);
    const float4* wp4 = (const float4*)(w + (size_t)lrow * K_DIM + kbase + kq * 8);

    // 16 warps: 4x4 grid of 32x32 output tiles.
    const int m0 = (wid >> 2) * 32;
    const int n0 = (wid & 3) * 32;

    float acc[2][4][4];
#pragma unroll
    for (int mi = 0; mi < 2; mi++)
#pragma unroll
        for (int nj = 0; nj < 4; nj++)
#pragma unroll
            for (int q = 0; q < 4; q++) acc[mi][nj][q] = 0.f;

    float4 rx[2], rw[2];
#pragma unroll
    for (int j = 0; j < 2; j++) { rx[j] = xp4[j]; rw[j] = wp4[j]; }

    float rsum = 0.f;

    for (int sub = 0; sub < NSUB; ++sub) {
        const int buf = sub & 1;

        uint2* adst = (uint2*)&sA[buf][lrow * LDSR + kq * 8];
        uint2* bdst = (uint2*)&sB[buf][lrow * LDSR + kq * 8];
#pragma unroll
        for (int j = 0; j < 2; j++) {
            float ax = __expf(rx[j].x), ay = __expf(rx[j].y);
            float az = __expf(rx[j].z), aw = __expf(rx[j].w);
            uint2 av;
            av.x = bf2_bits(__floats2bfloat162_rn(ax, ay));
            av.y = bf2_bits(__floats2bfloat162_rn(az, aw));
            adst[j] = av;
            float bx = __expf(rw[j].x), by = __expf(rw[j].y);
            float bz = __expf(rw[j].z), bw = __expf(rw[j].w);
            rsum += (bx + by) + (bz + bw);
            uint2 bv;
            bv.x = bf2_bits(__floats2bfloat162_rn(bx, by));
            bv.y = bf2_bits(__floats2bfloat162_rn(bz, bw));
            bdst[j] = bv;
        }

        if (sub + 1 < NSUB) {
#pragma unroll
            for (int j = 0; j < 2; j++) {
                rx[j] = xp4[(sub + 1) * 8 + j];
                rw[j] = wp4[(sub + 1) * 8 + j];
            }
        }

        __syncthreads();

#pragma unroll
        for (int ks = 0; ks < KSUB; ks += 16) {
            uint32_t af[2][4];
#pragma unroll
            for (int mi = 0; mi < 2; mi++) {
                int ar = m0 + mi * 16 + (lane & 15);
                int ac = ks + (lane >> 4) * 8;
                uint32_t addr = smem_u32(&sA[buf][ar * LDSR + ac]);
                asm volatile(
                    "ldmatrix.sync.aligned.m8n8.x4.shared.b16 {%0,%1,%2,%3}, [%4];"
                    : "=r"(af[mi][0]), "=r"(af[mi][1]), "=r"(af[mi][2]), "=r"(af[mi][3])
                    : "r"(addr));
            }
            uint32_t bfr[2][4];
#pragma unroll
            for (int nb = 0; nb < 2; nb++) {
                int g = lane >> 3, r = lane & 7;
                int br = n0 + nb * 16 + (g >> 1) * 8 + r;
                int bc = ks + (g & 1) * 8;
                uint32_t addr = smem_u32(&sB[buf][br * LDSR + bc]);
                asm volatile(
                    "ldmatrix.sync.aligned.m8n8.x4.shared.b16 {%0,%1,%2,%3}, [%4];"
                    : "=r"(bfr[nb][0]), "=r"(bfr[nb][1]), "=r"(bfr[nb][2]), "=r"(bfr[nb][3])
                    : "r"(addr));
            }
#pragma unroll
            for (int mi = 0; mi < 2; mi++)
#pragma unroll
                for (int nj = 0; nj < 4; nj++) {
                    uint32_t b0 = bfr[nj >> 1][(nj & 1) * 2 + 0];
                    uint32_t b1 = bfr[nj >> 1][(nj & 1) * 2 + 1];
                    asm volatile(
                        "mma.sync.aligned.m16n8k16.row.col.f32.bf16.bf16.f32 "
                        "{%0,%1,%2,%3}, {%4,%5,%6,%7}, {%8,%9}, {%0,%1,%2,%3};"
                        : "+f"(acc[mi][nj][0]), "+f"(acc[mi][nj][1]),
                          "+f"(acc[mi][nj][2]), "+f"(acc[mi][nj][3])
                        : "r"(af[mi][0]), "r"(af[mi][1]), "r"(af[mi][2]), "r"(af[mi][3]),
                          "r"(b0), "r"(b1));
                }
        }
    }

    // rsum partial: 4 threads/row -> pairwise shfl reduce
    rsum += __shfl_xor_sync(0xffffffffu, rsum, 1);
    rsum += __shfl_xor_sync(0xffffffffu, rsum, 2);
    if (kq == 0) g_rpart[bid * O_DIM + lrow] = rsum;

    // fp16 partial tile, transposed layout [b][sp][o2]
#pragma unroll
    for (int mi = 0; mi < 2; mi++)
#pragma unroll
        for (int nj = 0; nj < 4; nj++) {
            int gr = m0 + mi * 16 + (lane >> 2);
            int gc = n0 + nj * 8 + (lane & 3) * 2;
            g_part[(size_t)gr * (NSPLIT * 64) + bid * 64 + (gc >> 1)] =
                __floats2half2_rn(acc[mi][nj][0], acc[mi][nj][1]);
            g_part[(size_t)(gr + 8) * (NSPLIT * 64) + bid * 64 + (gc >> 1)] =
                __floats2half2_rn(acc[mi][nj][2], acc[mi][nj][3]);
        }

    // ---- software grid barrier (monotonic epoch; replay-safe) ----
    __threadfence();
    __syncthreads();                 // all stores of this block issued
    if (tid == 0) {
        int e0 = atomicAdd(&g_epoch, 0);          // baseline BEFORE arrival
        int old = atomicAdd(&g_arrive, 1);
        if (((old + 1) & (NSPLIT - 1)) == 0) {
            __threadfence();
            atomicAdd(&g_epoch, 1);               // release
        } else {
            while (atomicAdd(&g_epoch, 0) == e0) { }   // spin (acquire-ish)
        }
    }
    __syncthreads();
    __threadfence();                 // acquire for all threads

    // ---- reduce phase: this block owns batch row b = bid ----
    {
        const int b = bid;
        const __half2* pp = g_part + (size_t)b * (NSPLIT * 64);

        // S: 8 groups x 16 splits, 64 half2 outputs per group
        const int o2 = tid & 63;
        const int sg = tid >> 6;
        float s0 = 0.f, s1 = 0.f;
#pragma unroll
        for (int i = 0; i < 16; i++) {
            int sp = sg * 16 + i;
            __half2 h = __ldcg(pp + sp * 64 + o2);
            float2 v = __half22float2(h);
            s0 += v.x; s1 += v.y;
        }

        // R: 4 groups x 32 splits, 128 outputs per group
        const int oo = tid & 127;
        const int rg = tid >> 7;
        float r = 0.f;
#pragma unroll
        for (int i = 0; i < 32; i++)
            r += __ldcg(&g_rpart[(rg * 32 + i) * O_DIM + oo]);

        // smem reduce (overlay on sA — GEMM smem is dead now)
        float2* ss = (float2*)&sA[0][0];           // [8][64]
        float*  sr = (float*)(ss + 8 * 64);        // [4][128]
        __syncthreads();                           // cover overlay WAR
        ss[sg * 64 + o2] = make_float2(s0, s1);
        sr[rg * 128 + oo] = r;
        __syncthreads();

        if (tid < 64) {
            float S0 = 0.f, S1 = 0.f, R0 = 0.f, R1 = 0.f;
#pragma unroll
            for (int i = 0; i < 8; i++) {
                float2 v = ss[i * 64 + tid];
                S0 += v.x; S1 += v.y;
            }
#pragma unroll
            for (int i = 0; i < 4; i++) {
                R0 += sr[i * 128 + 2 * tid];
                R1 += sr[i * 128 + 2 * tid + 1];
            }
            *(float2*)&out[b * O_DIM + 2 * tid] =
                make_float2(__logf(S0) - __logf(R0), __logf(S1) - __logf(R1));
        }
    }
}

extern "C" void kernel_launch(void* const* d_in, const int* in_sizes, int n_in,
                              void* d_out, int out_size) {
    (void)in_sizes; (void)n_in; (void)out_size;
    const float* x = (const float*)d_in[0];   // [128, 16384]
    const float* w = (const float*)d_in[1];   // [128, 16384]
    float* out = (float*)d_out;               // [128, 128]

    srl_fused_kernel<<<NSPLIT, 512>>>(x, w, out);
}

// round 7
// speedup vs baseline: 1.0174x; 1.0174x over previous
#include <cuda_runtime.h>
#include <cuda_bf16.h>
#include <cuda_fp16.h>
#include <cstdint>

// ============================================================================
// out[b,o] = log( sum_k e^x[b,k] * e^w[o,k] ) - log( sum_k e^w[o,k] )
// Single fused kernel: split-K bf16 MMA GEMM -> software grid barrier
// (volatile-poll + nanosleep, monotonic epoch => graph-replay safe) ->
// in-kernel split reduce + log epilogue. Grid = 128 blocks = 1 wave.
// ============================================================================

#define B_DIM  128
#define O_DIM  128
#define K_DIM  16384
#define NSPLIT 128
#define KCHUNK 128
#define NSUB   4
#define KSUB   32
#define LDSR   40     // smem row stride (bf16): 80B, conflict-free ldmatrix

// Transposed partials: [b][sp][o2] -> reduce phase reads contiguous 32KB/block
__device__ __half2 g_part[B_DIM * NSPLIT * (O_DIM / 2)];
__device__ float   g_rpart[NSPLIT * O_DIM];     // [sp][o]
__device__ int     g_arrive;                    // monotonic across replays
__device__ int     g_epoch;                     // monotonic across replays

__device__ __forceinline__ uint32_t smem_u32(const void* p) {
    return (uint32_t)__cvta_generic_to_shared(p);
}
__device__ __forceinline__ uint32_t bf2_bits(__nv_bfloat162 v) {
    union { __nv_bfloat162 h; uint32_t u; } cvt; cvt.h = v; return cvt.u;
}

__global__ __launch_bounds__(512, 1)
void srl_fused_kernel(const float* __restrict__ x, const float* __restrict__ w,
                      float* __restrict__ out) {
    __shared__ __align__(16) __nv_bfloat16 sA[2][B_DIM * LDSR];
    __shared__ __align__(16) __nv_bfloat16 sB[2][B_DIM * LDSR];

    const int tid  = threadIdx.x;
    const int lane = tid & 31;
    const int wid  = tid >> 5;
    const int bid  = blockIdx.x;        // = split index sp, and = batch row b
    const int kbase = bid * KCHUNK;

    // Loaders: 4 threads/row, 8 contiguous k (32B) each per stage.
    const int lrow = tid >> 2;
    const int kq   = tid & 3;
    const float4* xp4 = (const float4*)(x + (size_t)lrow * K_DIM + kbase + kq * 8);
    const float4* wp4 = (const float4*)(w + (size_t)lrow * K_DIM + kbase + kq * 8);

    // 16 warps: 4x4 grid of 32x32 output tiles.
    const int m0 = (wid >> 2) * 32;
    const int n0 = (wid & 3) * 32;

    float4 rx[2], rw[2];                 // current-stage data (prefetched)
#pragma unroll
    for (int j = 0; j < 2; j++) { rx[j] = xp4[j]; rw[j] = wp4[j]; }

    float acc[2][4][4];
#pragma unroll
    for (int mi = 0; mi < 2; mi++)
#pragma unroll
        for (int nj = 0; nj < 4; nj++)
#pragma unroll
            for (int q = 0; q < 4; q++) acc[mi][nj][q] = 0.f;

    float rsum = 0.f;

    for (int sub = 0; sub < NSUB; ++sub) {
        const int buf = sub & 1;
        const bool has_next = (sub + 1 < NSUB);

        uint2* adst = (uint2*)&sA[buf][lrow * LDSR + kq * 8];
        uint2* bdst = (uint2*)&sB[buf][lrow * LDSR + kq * 8];
        // exp/convert/store each float4, then IMMEDIATELY reload that register
        // with next-stage data: next LDGs issue mid-stage, hiding DRAM latency.
#pragma unroll
        for (int j = 0; j < 2; j++) {
            float ax = __expf(rx[j].x), ay = __expf(rx[j].y);
            float az = __expf(rx[j].z), aw = __expf(rx[j].w);
            if (has_next) rx[j] = xp4[(sub + 1) * 8 + j];
            uint2 av;
            av.x = bf2_bits(__floats2bfloat162_rn(ax, ay));
            av.y = bf2_bits(__floats2bfloat162_rn(az, aw));
            adst[j] = av;
            float bx = __expf(rw[j].x), by = __expf(rw[j].y);
            float bz = __expf(rw[j].z), bw = __expf(rw[j].w);
            if (has_next) rw[j] = wp4[(sub + 1) * 8 + j];
            rsum += (bx + by) + (bz + bw);
            uint2 bv;
            bv.x = bf2_bits(__floats2bfloat162_rn(bx, by));
            bv.y = bf2_bits(__floats2bfloat162_rn(bz, bw));
            bdst[j] = bv;
        }

        __syncthreads();

#pragma unroll
        for (int ks = 0; ks < KSUB; ks += 16) {
            uint32_t af[2][4];
#pragma unroll
            for (int mi = 0; mi < 2; mi++) {
                int ar = m0 + mi * 16 + (lane & 15);
                int ac = ks + (lane >> 4) * 8;
                uint32_t addr = smem_u32(&sA[buf][ar * LDSR + ac]);
                asm volatile(
                    "ldmatrix.sync.aligned.m8n8.x4.shared.b16 {%0,%1,%2,%3}, [%4];"
                    : "=r"(af[mi][0]), "=r"(af[mi][1]), "=r"(af[mi][2]), "=r"(af[mi][3])
                    : "r"(addr));
            }
            uint32_t bfr[2][4];
#pragma unroll
            for (int nb = 0; nb < 2; nb++) {
                int g = lane >> 3, r = lane & 7;
                int br = n0 + nb * 16 + (g >> 1) * 8 + r;
                int bc = ks + (g & 1) * 8;
                uint32_t addr = smem_u32(&sB[buf][br * LDSR + bc]);
                asm volatile(
                    "ldmatrix.sync.aligned.m8n8.x4.shared.b16 {%0,%1,%2,%3}, [%4];"
                    : "=r"(bfr[nb][0]), "=r"(bfr[nb][1]), "=r"(bfr[nb][2]), "=r"(bfr[nb][3])
                    : "r"(addr));
            }
#pragma unroll
            for (int mi = 0; mi < 2; mi++)
#pragma unroll
                for (int nj = 0; nj < 4; nj++) {
                    uint32_t b0 = bfr[nj >> 1][(nj & 1) * 2 + 0];
                    uint32_t b1 = bfr[nj >> 1][(nj & 1) * 2 + 1];
                    asm volatile(
                        "mma.sync.aligned.m16n8k16.row.col.f32.bf16.bf16.f32 "
                        "{%0,%1,%2,%3}, {%4,%5,%6,%7}, {%8,%9}, {%0,%1,%2,%3};"
                        : "+f"(acc[mi][nj][0]), "+f"(acc[mi][nj][1]),
                          "+f"(acc[mi][nj][2]), "+f"(acc[mi][nj][3])
                        : "r"(af[mi][0]), "r"(af[mi][1]), "r"(af[mi][2]), "r"(af[mi][3]),
                          "r"(b0), "r"(b1));
                }
        }
    }

    // rsum partial: 4 threads/row -> pairwise shfl reduce
    rsum += __shfl_xor_sync(0xffffffffu, rsum, 1);
    rsum += __shfl_xor_sync(0xffffffffu, rsum, 2);
    if (kq == 0) g_rpart[bid * O_DIM + lrow] = rsum;

    // fp16 partial tile, transposed layout [b][sp][o2]
#pragma unroll
    for (int mi = 0; mi < 2; mi++)
#pragma unroll
        for (int nj = 0; nj < 4; nj++) {
            int gr = m0 + mi * 16 + (lane >> 2);
            int gc = n0 + nj * 8 + (lane & 3) * 2;
            g_part[(size_t)gr * (NSPLIT * 64) + bid * 64 + (gc >> 1)] =
                __floats2half2_rn(acc[mi][nj][0], acc[mi][nj][1]);
            g_part[(size_t)(gr + 8) * (NSPLIT * 64) + bid * 64 + (gc >> 1)] =
                __floats2half2_rn(acc[mi][nj][2], acc[mi][nj][3]);
        }

    // ---- software grid barrier: volatile poll + nanosleep (no atomic spin) ----
    __threadfence();                 // each thread's stores globally visible
    __syncthreads();                 // ... before tid0 arrives
    if (tid == 0) {
        // e0 read happens BEFORE our arrival, so this round's release cannot
        // have occurred yet; previous launches fully settled (graph serializes).
        int e0 = *(volatile int*)&g_epoch;
        int old = atomicAdd(&g_arrive, 1);
        if (((old + 1) & (NSPLIT - 1)) == 0) {
            __threadfence();
            atomicAdd(&g_epoch, 1);               // release
        } else {
            while (*(volatile int*)&g_epoch == e0) __nanosleep(64);
        }
    }
    __syncthreads();
    __threadfence();

    // ---- reduce phase: this block owns batch row b = bid ----
    {
        const int b = bid;
        const __half2* pp = g_part + (size_t)b * (NSPLIT * 64);

        // S: 8 groups x 16 splits, 64 half2 outputs per group (coalesced 128B/warp)
        const int o2 = tid & 63;
        const int sg = tid >> 6;          // 0..7
        float s0 = 0.f, s1 = 0.f;
#pragma unroll
        for (int i = 0; i < 16; i++) {
            int sp = sg * 16 + i;
            float2 v = __half22float2(__ldcg(pp + sp * 64 + o2));
            s0 += v.x; s1 += v.y;
        }

        // R: 4 groups x 32 splits, 128 outputs per group
        const int oo = tid & 127;
        const int rg = tid >> 7;          // 0..3 (512 threads)
        float r = 0.f;
#pragma unroll
        for (int i = 0; i < 32; i++)
            r += __ldcg(&g_rpart[(rg * 32 + i) * O_DIM + oo]);

        // smem reduce (overlay on sA -- GEMM smem is dead now)
        float2* ss = (float2*)&sA[0][0];           // [8][64] float2 = 4KB
        float*  sr = (float*)(ss + 8 * 64);        // [4][128] float = 2KB
        __syncthreads();                           // cover overlay WAR
        ss[sg * 64 + o2] = make_float2(s0, s1);
        sr[rg * 128 + oo] = r;
        __syncthreads();

        if (tid < 64) {
            float S0 = 0.f, S1 = 0.f, R0 = 0.f, R1 = 0.f;
#pragma unroll
            for (int i = 0; i < 8; i++) {
                float2 v = ss[i * 64 + tid];
                S0 += v.x; S1 += v.y;
            }
#pragma unroll
            for (int i = 0; i < 4; i++) {
                R0 += sr[i * 128 + 2 * tid];
                R1 += sr[i * 128 + 2 * tid + 1];
            }
            *(float2*)&out[b * O_DIM + 2 * tid] =
                make_float2(__logf(S0) - __logf(R0), __logf(S1) - __logf(R1));
        }
    }
}

extern "C" void kernel_launch(void* const* d_in, const int* in_sizes, int n_in,
                              void* d_out, int out_size) {
    (void)in_sizes; (void)n_in; (void)out_size;
    const float* x = (const float*)d_in[0];   // [128, 16384]
    const float* w = (const float*)d_in[1];   // [128, 16384]
    float* out = (float*)d_out;               // [128, 128]

    srl_fused_kernel<<<NSPLIT, 512>>>(x, w, out);
}

// round 8
// speedup vs baseline: 1.0445x; 1.0267x over previous
#include <cuda_runtime.h>
#include <cuda_bf16.h>
#include <cuda_fp16.h>
#include <cstdint>

// ============================================================================
// out[b,o] = log( sum_k e^x[b,k] * e^w[o,k] ) - log( sum_k e^w[o,k] )
// Split kernels. GEMM: 256 blocks x 256 threads, 2 CTAs/SM, each block does a
// 128x64 half-tile over a K=128 slice (block = (sp, nhalf)). Finalize: 128
// blocks x 1024 threads, 32-way sp-parallel reduce + log.
// ============================================================================

#define B_DIM  128
#define O_DIM  128
#define K_DIM  16384
#define NSPLIT 128
#define KCHUNK 128
#define NSUB   4
#define KSUB   32
#define LDSR   40     // smem row stride (bf16): 80B, conflict-free ldmatrix

__device__ __half2 g_part[NSPLIT * B_DIM * (O_DIM / 2)];  // [sp][b][o2] 4MB
__device__ float   g_rpart[NSPLIT * O_DIM];               // [sp][o]

__device__ __forceinline__ uint32_t smem_u32(const void* p) {
    return (uint32_t)__cvta_generic_to_shared(p);
}
__device__ __forceinline__ uint32_t bf2_bits(__nv_bfloat162 v) {
    union { __nv_bfloat162 h; uint32_t u; } cvt; cvt.h = v; return cvt.u;
}

__global__ __launch_bounds__(256, 2)
void srl_gemm_kernel(const float* __restrict__ x, const float* __restrict__ w) {
    __shared__ __align__(16) __nv_bfloat16 sA[2][B_DIM * LDSR];       // 128 x-rows
    __shared__ __align__(16) __nv_bfloat16 sB[2][(O_DIM / 2) * LDSR]; //  64 w-rows

    const int tid  = threadIdx.x;
    const int lane = tid & 31;
    const int wid  = tid >> 5;          // 0..7
    const int sp   = blockIdx.x >> 1;   // K-split index
    const int nh   = blockIdx.x & 1;    // which 64-wide output half
    const int kbase = sp * KCHUNK;

    // A loaders: 2 threads per x-row, each owns 16 contiguous f32 (64B)/stage.
    const int lrowA = tid >> 1;
    const int kqA   = tid & 1;
    const float4* xp4 = (const float4*)(x + (size_t)lrowA * K_DIM + kbase + kqA * 16);
    // B loaders: 4 threads per w-row (rows nh*64 .. +63), 8 f32 (32B)/stage.
    const int lrowW = tid >> 2;         // 0..63
    const int kqW   = tid & 3;
    const float4* wp4 = (const float4*)(w + (size_t)(nh * 64 + lrowW) * K_DIM + kbase + kqW * 8);

    // 8 warps: 4(m) x 2(n) grid of 32x32 tiles covering 128x64.
    const int m0 = (wid >> 1) * 32;
    const int n0 = (wid & 1) * 32;

    float acc[2][4][4];
#pragma unroll
    for (int mi = 0; mi < 2; mi++)
#pragma unroll
        for (int nj = 0; nj < 4; nj++)
#pragma unroll
            for (int q = 0; q < 4; q++) acc[mi][nj][q] = 0.f;

    float4 rxA[4], rwB[2];
#pragma unroll
    for (int j = 0; j < 4; j++) rxA[j] = xp4[j];
#pragma unroll
    for (int j = 0; j < 2; j++) rwB[j] = wp4[j];

    float rsum = 0.f;

    for (int sub = 0; sub < NSUB; ++sub) {
        const int buf = sub & 1;
        const bool has_next = (sub + 1 < NSUB);

        uint2* adst = (uint2*)&sA[buf][lrowA * LDSR + kqA * 16];
        uint2* bdst = (uint2*)&sB[buf][lrowW * LDSR + kqW * 8];
#pragma unroll
        for (int j = 0; j < 4; j++) {
            float ax = __expf(rxA[j].x), ay = __expf(rxA[j].y);
            float az = __expf(rxA[j].z), aw = __expf(rxA[j].w);
            if (has_next) rxA[j] = xp4[(sub + 1) * 8 + j];
            uint2 av;
            av.x = bf2_bits(__floats2bfloat162_rn(ax, ay));
            av.y = bf2_bits(__floats2bfloat162_rn(az, aw));
            adst[j] = av;
        }
#pragma unroll
        for (int j = 0; j < 2; j++) {
            float bx = __expf(rwB[j].x), by = __expf(rwB[j].y);
            float bz = __expf(rwB[j].z), bw = __expf(rwB[j].w);
            if (has_next) rwB[j] = wp4[(sub + 1) * 8 + j];
            rsum += (bx + by) + (bz + bw);
            uint2 bv;
            bv.x = bf2_bits(__floats2bfloat162_rn(bx, by));
            bv.y = bf2_bits(__floats2bfloat162_rn(bz, bw));
            bdst[j] = bv;
        }

        __syncthreads();

#pragma unroll
        for (int ks = 0; ks < KSUB; ks += 16) {
            uint32_t af[2][4];
#pragma unroll
            for (int mi = 0; mi < 2; mi++) {
                int ar = m0 + mi * 16 + (lane & 15);
                int ac = ks + (lane >> 4) * 8;
                uint32_t addr = smem_u32(&sA[buf][ar * LDSR + ac]);
                asm volatile(
                    "ldmatrix.sync.aligned.m8n8.x4.shared.b16 {%0,%1,%2,%3}, [%4];"
                    : "=r"(af[mi][0]), "=r"(af[mi][1]), "=r"(af[mi][2]), "=r"(af[mi][3])
                    : "r"(addr));
            }
            uint32_t bfr[2][4];
#pragma unroll
            for (int nb = 0; nb < 2; nb++) {
                int g = lane >> 3, r = lane & 7;
                int br = n0 + nb * 16 + (g >> 1) * 8 + r;
                int bc = ks + (g & 1) * 8;
                uint32_t addr = smem_u32(&sB[buf][br * LDSR + bc]);
                asm volatile(
                    "ldmatrix.sync.aligned.m8n8.x4.shared.b16 {%0,%1,%2,%3}, [%4];"
                    : "=r"(bfr[nb][0]), "=r"(bfr[nb][1]), "=r"(bfr[nb][2]), "=r"(bfr[nb][3])
                    : "r"(addr));
            }
#pragma unroll
            for (int mi = 0; mi < 2; mi++)
#pragma unroll
                for (int nj = 0; nj < 4; nj++) {
                    uint32_t b0 = bfr[nj >> 1][(nj & 1) * 2 + 0];
                    uint32_t b1 = bfr[nj >> 1][(nj & 1) * 2 + 1];
                    asm volatile(
                        "mma.sync.aligned.m16n8k16.row.col.f32.bf16.bf16.f32 "
                        "{%0,%1,%2,%3}, {%4,%5,%6,%7}, {%8,%9}, {%0,%1,%2,%3};"
                        : "+f"(acc[mi][nj][0]), "+f"(acc[mi][nj][1]),
                          "+f"(acc[mi][nj][2]), "+f"(acc[mi][nj][3])
                        : "r"(af[mi][0]), "r"(af[mi][1]), "r"(af[mi][2]), "r"(af[mi][3]),
                          "r"(b0), "r"(b1));
                }
        }
    }

    // rsum: 4 threads per w-row -> pairwise shfl reduce (lanes of a row adjacent)
    rsum += __shfl_xor_sync(0xffffffffu, rsum, 1);
    rsum += __shfl_xor_sync(0xffffffffu, rsum, 2);
    if (kqW == 0) g_rpart[sp * O_DIM + nh * 64 + lrowW] = rsum;

    // fp16 partials [sp][b][o2]; this block owns o2 range nh*32..+31
#pragma unroll
    for (int mi = 0; mi < 2; mi++)
#pragma unroll
        for (int nj = 0; nj < 4; nj++) {
            int gr  = m0 + mi * 16 + (lane >> 2);
            int gcl = n0 + nj * 8 + (lane & 3) * 2;           // local 0..63
            int o2g = nh * 32 + (gcl >> 1);
            g_part[(size_t)sp * (B_DIM * 64) + gr * 64 + o2g] =
                __floats2half2_rn(acc[mi][nj][0], acc[mi][nj][1]);
            g_part[(size_t)sp * (B_DIM * 64) + (gr + 8) * 64 + o2g] =
                __floats2half2_rn(acc[mi][nj][2], acc[mi][nj][3]);
        }
}

// Finalize: block b; 32 sp-groups x 32 o4-slots; 4 outputs per o4-slot.
__global__ __launch_bounds__(1024)
void srl_finalize_kernel(float* __restrict__ out) {
    const int b  = blockIdx.x;
    const int t  = threadIdx.x;
    const int o4 = t & 31;        // outputs 4*o4 .. 4*o4+3
    const int sg = t >> 5;        // 0..31

    float s0 = 0.f, s1 = 0.f, s2 = 0.f, s3 = 0.f;
    float r0 = 0.f, r1 = 0.f, r2 = 0.f, r3 = 0.f;
#pragma unroll
    for (int i = 0; i < 4; i++) {
        int sp = sg + 32 * i;
        uint2 pv = *(const uint2*)&g_part[(size_t)sp * (B_DIM * 64) + b * 64 + o4 * 2];
        union { uint32_t u; __half2 h; } c0, c1;
        c0.u = pv.x; c1.u = pv.y;
        float2 v0 = __half22float2(c0.h);
        float2 v1 = __half22float2(c1.h);
        s0 += v0.x; s1 += v0.y; s2 += v1.x; s3 += v1.y;
        float4 rv = *(const float4*)&g_rpart[sp * O_DIM + o4 * 4];
        r0 += rv.x; r1 += rv.y; r2 += rv.z; r3 += rv.w;
    }

    __shared__ float ss[32 * 128];   // [sg][o]
    __shared__ float sr[32 * 128];
    *(float4*)&ss[sg * 128 + o4 * 4] = make_float4(s0, s1, s2, s3);
    *(float4*)&sr[sg * 128 + o4 * 4] = make_float4(r0, r1, r2, r3);
    __syncthreads();

    if (t < 128) {
        float S = 0.f, R = 0.f;
#pragma unroll
        for (int i = 0; i < 32; i++) {
            S += ss[i * 128 + t];
            R += sr[i * 128 + t];
        }
        out[b * O_DIM + t] = __logf(S) - __logf(R);
    }
}

extern "C" void kernel_launch(void* const* d_in, const int* in_sizes, int n_in,
                              void* d_out, int out_size) {
    (void)in_sizes; (void)n_in; (void)out_size;
    const float* x = (const float*)d_in[0];   // [128, 16384]
    const float* w = (const float*)d_in[1];   // [128, 16384]
    float* out = (float*)d_out;               // [128, 128]

    srl_gemm_kernel<<<NSPLIT * 2, 256>>>(x, w);
    srl_finalize_kernel<<<B_DIM, 1024>>>(out);
}

// round 9
// speedup vs baseline: 1.1934x; 1.1425x over previous
#include <cuda_runtime.h>
#include <cuda_bf16.h>
#include <cuda_fp16.h>
#include <cstdint>

// ============================================================================
// out[b,o] = log( sum_k e^x[b,k] * e^w[o,k] ) - log( sum_k e^w[o,k] )
// R4 GEMM (best measured: 128 blocks x 512 thr, bf16 MMA, fp16 partials)
// + finalize launched via PDL so its launch/ramp overlaps the GEMM tail.
// ============================================================================

#define B_DIM  128
#define O_DIM  128
#define K_DIM  16384
#define NSPLIT 128
#define KCHUNK 128
#define NSUB   4
#define KSUB   32
#define LDSR   40     // smem row stride (bf16): 80B, conflict-free ldmatrix

__device__ __half2 g_part[NSPLIT * B_DIM * (O_DIM / 2)];  // [sp][b][o2] 4MB
__device__ float   g_rpart[NSPLIT * O_DIM];               // [sp][o]

__device__ __forceinline__ uint32_t smem_u32(const void* p) {
    return (uint32_t)__cvta_generic_to_shared(p);
}
__device__ __forceinline__ uint32_t bf2_bits(__nv_bfloat162 v) {
    union { __nv_bfloat162 h; uint32_t u; } cvt; cvt.h = v; return cvt.u;
}

__global__ __launch_bounds__(512, 1)
void srl_gemm_kernel(const float* __restrict__ x, const float* __restrict__ w) {
    __shared__ __align__(16) __nv_bfloat16 sA[2][B_DIM * LDSR];
    __shared__ __align__(16) __nv_bfloat16 sB[2][B_DIM * LDSR];

    const int tid  = threadIdx.x;
    const int lane = tid & 31;
    const int wid  = tid >> 5;
    const int bid  = blockIdx.x;
    const int kbase = bid * KCHUNK;

    const int lrow = tid >> 2;
    const int kq   = tid & 3;
    const float4* xp4 = (const float4*)(x + (size_t)lrow * K_DIM + kbase + kq * 8);
    const float4* wp4 = (const float4*)(w + (size_t)lrow * K_DIM + kbase + kq * 8);

    const int m0 = (wid >> 2) * 32;
    const int n0 = (wid & 3) * 32;

    float acc[2][4][4];
#pragma unroll
    for (int mi = 0; mi < 2; mi++)
#pragma unroll
        for (int nj = 0; nj < 4; nj++)
#pragma unroll
            for (int q = 0; q < 4; q++) acc[mi][nj][q] = 0.f;

    float4 rx[2], rw[2];
#pragma unroll
    for (int j = 0; j < 2; j++) { rx[j] = xp4[j]; rw[j] = wp4[j]; }

    float rsum = 0.f;

    for (int sub = 0; sub < NSUB; ++sub) {
        const int buf = sub & 1;
        const bool has_next = (sub + 1 < NSUB);

        uint2* adst = (uint2*)&sA[buf][lrow * LDSR + kq * 8];
        uint2* bdst = (uint2*)&sB[buf][lrow * LDSR + kq * 8];
#pragma unroll
        for (int j = 0; j < 2; j++) {
            float ax = __expf(rx[j].x), ay = __expf(rx[j].y);
            float az = __expf(rx[j].z), aw = __expf(rx[j].w);
            if (has_next) rx[j] = xp4[(sub + 1) * 8 + j];
            uint2 av;
            av.x = bf2_bits(__floats2bfloat162_rn(ax, ay));
            av.y = bf2_bits(__floats2bfloat162_rn(az, aw));
            adst[j] = av;
            float bx = __expf(rw[j].x), by = __expf(rw[j].y);
            float bz = __expf(rw[j].z), bw = __expf(rw[j].w);
            if (has_next) rw[j] = wp4[(sub + 1) * 8 + j];
            rsum += (bx + by) + (bz + bw);
            uint2 bv;
            bv.x = bf2_bits(__floats2bfloat162_rn(bx, by));
            bv.y = bf2_bits(__floats2bfloat162_rn(bz, bw));
            bdst[j] = bv;
        }

        __syncthreads();

#pragma unroll
        for (int ks = 0; ks < KSUB; ks += 16) {
            uint32_t af[2][4];
#pragma unroll
            for (int mi = 0; mi < 2; mi++) {
                int ar = m0 + mi * 16 + (lane & 15);
                int ac = ks + (lane >> 4) * 8;
                uint32_t addr = smem_u32(&sA[buf][ar * LDSR + ac]);
                asm volatile(
                    "ldmatrix.sync.aligned.m8n8.x4.shared.b16 {%0,%1,%2,%3}, [%4];"
                    : "=r"(af[mi][0]), "=r"(af[mi][1]), "=r"(af[mi][2]), "=r"(af[mi][3])
                    : "r"(addr));
            }
            uint32_t bfr[2][4];
#pragma unroll
            for (int nb = 0; nb < 2; nb++) {
                int g = lane >> 3, r = lane & 7;
                int br = n0 + nb * 16 + (g >> 1) * 8 + r;
                int bc = ks + (g & 1) * 8;
                uint32_t addr = smem_u32(&sB[buf][br * LDSR + bc]);
                asm volatile(
                    "ldmatrix.sync.aligned.m8n8.x4.shared.b16 {%0,%1,%2,%3}, [%4];"
                    : "=r"(bfr[nb][0]), "=r"(bfr[nb][1]), "=r"(bfr[nb][2]), "=r"(bfr[nb][3])
                    : "r"(addr));
            }
#pragma unroll
            for (int mi = 0; mi < 2; mi++)
#pragma unroll
                for (int nj = 0; nj < 4; nj++) {
                    uint32_t b0 = bfr[nj >> 1][(nj & 1) * 2 + 0];
                    uint32_t b1 = bfr[nj >> 1][(nj & 1) * 2 + 1];
                    asm volatile(
                        "mma.sync.aligned.m16n8k16.row.col.f32.bf16.bf16.f32 "
                        "{%0,%1,%2,%3}, {%4,%5,%6,%7}, {%8,%9}, {%0,%1,%2,%3};"
                        : "+f"(acc[mi][nj][0]), "+f"(acc[mi][nj][1]),
                          "+f"(acc[mi][nj][2]), "+f"(acc[mi][nj][3])
                        : "r"(af[mi][0]), "r"(af[mi][1]), "r"(af[mi][2]), "r"(af[mi][3]),
                          "r"(b0), "r"(b1));
                }
        }
    }

    rsum += __shfl_xor_sync(0xffffffffu, rsum, 1);
    rsum += __shfl_xor_sync(0xffffffffu, rsum, 2);
    if (kq == 0) g_rpart[bid * O_DIM + lrow] = rsum;

#pragma unroll
    for (int mi = 0; mi < 2; mi++)
#pragma unroll
        for (int nj = 0; nj < 4; nj++) {
            int gr = m0 + mi * 16 + (lane >> 2);
            int gc = n0 + nj * 8 + (lane & 3) * 2;
            g_part[(size_t)bid * (B_DIM * 64) + gr * 64 + (gc >> 1)] =
                __floats2half2_rn(acc[mi][nj][0], acc[mi][nj][1]);
            g_part[(size_t)bid * (B_DIM * 64) + (gr + 8) * 64 + (gc >> 1)] =
                __floats2half2_rn(acc[mi][nj][2], acc[mi][nj][3]);
        }

    // Allow the dependent finalize grid to begin launching (PDL).
    cudaTriggerProgrammaticLaunchCompletion();
}

// Finalize: block b; 32 sp-groups x 32 o4-slots; launched via PDL so its
// launch/ramp overlaps the GEMM tail. Loads happen only after the grid
// dependency resolves (producer stores visible).
__global__ __launch_bounds__(1024)
void srl_finalize_kernel(float* __restrict__ out) {
    const int b  = blockIdx.x;
    const int t  = threadIdx.x;
    const int o4 = t & 31;
    const int sg = t >> 5;

    // Prologue (address math) runs pre-dependency; then wait for GEMM grid.
    const __half2* pbase = g_part + (size_t)b * 64 + (size_t)sg * (B_DIM * 64) + o4 * 2;
    cudaGridDependencySynchronize();

    float s0 = 0.f, s1 = 0.f, s2 = 0.f, s3 = 0.f;
    float r0 = 0.f, r1 = 0.f, r2 = 0.f, r3 = 0.f;
#pragma unroll
    for (int i = 0; i < 4; i++) {
        int sp = sg + 32 * i;
        uint2 pv = *(const uint2*)(pbase + (size_t)(32 * i) * (B_DIM * 64));
        union { uint32_t u; __half2 h; } c0, c1;
        c0.u = pv.x; c1.u = pv.y;
        float2 v0 = __half22float2(c0.h);
        float2 v1 = __half22float2(c1.h);
        s0 += v0.x; s1 += v0.y; s2 += v1.x; s3 += v1.y;
        float4 rv = *(const float4*)&g_rpart[sp * O_DIM + o4 * 4];
        r0 += rv.x; r1 += rv.y; r2 += rv.z; r3 += rv.w;
    }

    __shared__ float ss[32 * 128];
    __shared__ float sr[32 * 128];
    *(float4*)&ss[sg * 128 + o4 * 4] = make_float4(s0, s1, s2, s3);
    *(float4*)&sr[sg * 128 + o4 * 4] = make_float4(r0, r1, r2, r3);
    __syncthreads();

    if (t < 128) {
        float S = 0.f, R = 0.f;
#pragma unroll
        for (int i = 0; i < 32; i++) {
            S += ss[i * 128 + t];
            R += sr[i * 128 + t];
        }
        out[b * O_DIM + t] = __logf(S) - __logf(R);
    }
}

extern "C" void kernel_launch(void* const* d_in, const int* in_sizes, int n_in,
                              void* d_out, int out_size) {
    (void)in_sizes; (void)n_in; (void)out_size;
    const float* x = (const float*)d_in[0];   // [128, 16384]
    const float* w = (const float*)d_in[1];   // [128, 16384]
    float* out = (float*)d_out;               // [128, 128]

    srl_gemm_kernel<<<NSPLIT, 512>>>(x, w);

    // PDL launch: finalize may begin while the GEMM grid is still running;
    // cudaGridDependencySynchronize() inside gates the actual reads.
    cudaLaunchConfig_t cfg = {};
    cfg.gridDim  = dim3(B_DIM);
    cfg.blockDim = dim3(1024);
    cfg.dynamicSmemBytes = 0;
    cfg.stream = 0;
    cudaLaunchAttribute attr[1];
    attr[0].id = cudaLaunchAttributeProgrammaticStreamSerialization;
    attr[0].val.programmaticStreamSerializationAllowed = 1;
    cfg.attrs = attr;
    cfg.numAttrs = 1;
    cudaLaunchKernelEx(&cfg, srl_finalize_kernel, out);
}